// round 6
// baseline (speedup 1.0000x reference)
#include <cuda_runtime.h>
#include <cuda_fp16.h>

#define N_NODES 100000
#define N_EDGES 1000000
#define N_GRAPHS 64
#define HD 64
#define EPSV 1e-5f

// ---------------- scratch (device globals; no allocation allowed) ------------
__device__ __half g_yh[N_NODES * HD];  // GEMM output (fp16, randomly gathered)
__device__ __half g_xh[N_NODES * HD];  // layer input X (fp16, for tensor-core A)
__device__ float g_xa[N_NODES * HD];   // ping (fp32 layer outputs, residual/pool)
__device__ float g_xb[N_NODES * HD];   // pong
__device__ int   g_deg[N_NODES];
__device__ float g_dinv[N_NODES];
__device__ int   g_rowptr[N_NODES + 1];
__device__ int   g_cursor[N_NODES];
__device__ int2  g_csr[N_EDGES];       // .x = src node, .y = bits of dinv[src]
__device__ int   g_partial[256];       // scan lookback state (agg+1, 0=not ready)
__device__ float g_ssum[N_GRAPHS * HD];
__device__ float g_cnt[N_GRAPHS];

// ---------------- setup 0: degree count + fused zeroing ----------------------
// g_deg is zeroed by a cudaMemsetAsync before this kernel.
__global__ void k_count(const int* __restrict__ dst) {
    int e = blockIdx.x * blockDim.x + threadIdx.x;
    if (e < N_EDGES) atomicAdd(&g_deg[dst[e]], 1);
    if (e < N_GRAPHS * HD) g_ssum[e] = 0.f;
    if (e < N_GRAPHS)      g_cnt[e]  = 0.f;
    if (e < 256)           g_partial[e] = 0;      // scan state reset
}

// ---------------- setup 1: single-pass scan + dinv ---------------------------
// 196 blocks x 512. Each block: local inclusive scan, publish aggregate,
// parallel-spin on all predecessors' aggregates, reduce -> block offset.
__global__ void k_scan() {
    __shared__ int sh[512];
    __shared__ int shp[256];
    int tid = threadIdx.x;
    int bid = blockIdx.x;
    int i = bid * 512 + tid;

    int v = (i < N_NODES) ? g_deg[i] : 0;        // edge count (no self loop)
    if (i < N_NODES) g_dinv[i] = rsqrtf((float)(v + 1));

    sh[tid] = v;
    __syncthreads();
    for (int off = 1; off < 512; off <<= 1) {
        int t = (tid >= off) ? sh[tid - off] : 0;
        __syncthreads();
        sh[tid] += t;
        __syncthreads();
    }
    int incl  = sh[tid];
    int total = sh[511];

    // publish aggregate (before waiting: no deadlock)
    if (tid == 0) {
        __threadfence();
        atomicExch(&g_partial[bid], total + 1);
    }

    // parallel spin on predecessors
    if (tid < 256) {
        int p = 0;
        if (tid < bid) {
            do { p = atomicAdd(&g_partial[tid], 0); } while (p == 0);
            p -= 1;
        }
        shp[tid] = p;
    }
    __syncthreads();
    for (int off = 128; off > 0; off >>= 1) {
        if (tid < off) shp[tid] += shp[tid + off];
        __syncthreads();
    }
    int offset = shp[0];

    if (i < N_NODES) {
        int ex = offset + incl - v;   // exclusive prefix
        g_rowptr[i] = ex;
        g_cursor[i] = ex;
    }
    if (bid == 0 && tid == 0) g_rowptr[N_NODES] = N_EDGES;
}

// ---------------- setup 2: scatter edges into CSR ----------------------------
__global__ void k_scatter(const int* __restrict__ src, const int* __restrict__ dst) {
    int e = blockIdx.x * blockDim.x + threadIdx.x;
    if (e >= N_EDGES) return;
    int d = dst[e];
    int s = src[e];
    int p = atomicAdd(&g_cursor[d], 1);
    g_csr[p] = make_int2(s, __float_as_int(g_dinv[s]));
}

// ---------------- GEMM via HMMA: Yh = half(X @ W) ----------------------------
// 128 threads (4 warps), block = 64 rows. Warp: 16 rows x 64 cols via
// m16n8k16, A preloaded (4 k-tiles), B frags from smem W^T (stride 72,
// conflict-free). ext!=0: A read from fp32 Xext with inline cvt.
__device__ __forceinline__ unsigned pack_h2(float a, float b) {
    __half2 h = __floats2half2_rn(a, b);
    return *(unsigned*)&h;
}

__global__ void __launch_bounds__(128) k_gemm(const float* __restrict__ Xext, int ext,
                                              const float* __restrict__ W) {
    __shared__ __half Wt[64 * 72];   // Wt[n][k], stride 72 halves
    int tid  = threadIdx.x;
    int lane = tid & 31;
    int wid  = tid >> 5;

    // stage W^T fp16: 2048 (n, k-pair) items
#pragma unroll
    for (int it = 0; it < 16; it++) {
        int idx = it * 128 + tid;          // 0..2047
        int k0  = (idx & 31) * 2;
        int n   = idx >> 5;
        float f0 = W[k0 * 64 + n];
        float f1 = W[(k0 + 1) * 64 + n];
        *(__half2*)&Wt[n * 72 + k0] = __floats2half2_rn(f0, f1);
    }
    __syncthreads();

    int m0 = blockIdx.x * 64 + wid * 16;
    int r  = lane >> 2;          // 0..7
    int q2 = (lane & 3) * 2;     // 0,2,4,6
    int row0 = m0 + r, row1 = m0 + r + 8;
    bool v0 = row0 < N_NODES, v1 = row1 < N_NODES;

    // preload A fragments, 4 k-tiles x 4 regs
    unsigned A[4][4];
#pragma unroll
    for (int kt = 0; kt < 4; kt++) {
        int k0 = kt * 16 + q2;
        if (ext) {
            float2 e0 = v0 ? *(const float2*)&Xext[(size_t)row0 * 64 + k0]     : make_float2(0.f, 0.f);
            float2 e1 = v1 ? *(const float2*)&Xext[(size_t)row1 * 64 + k0]     : make_float2(0.f, 0.f);
            float2 e2 = v0 ? *(const float2*)&Xext[(size_t)row0 * 64 + k0 + 8] : make_float2(0.f, 0.f);
            float2 e3 = v1 ? *(const float2*)&Xext[(size_t)row1 * 64 + k0 + 8] : make_float2(0.f, 0.f);
            A[kt][0] = pack_h2(e0.x, e0.y);
            A[kt][1] = pack_h2(e1.x, e1.y);
            A[kt][2] = pack_h2(e2.x, e2.y);
            A[kt][3] = pack_h2(e3.x, e3.y);
        } else {
            A[kt][0] = v0 ? *(const unsigned*)&g_xh[(size_t)row0 * 64 + k0]     : 0u;
            A[kt][1] = v1 ? *(const unsigned*)&g_xh[(size_t)row1 * 64 + k0]     : 0u;
            A[kt][2] = v0 ? *(const unsigned*)&g_xh[(size_t)row0 * 64 + k0 + 8] : 0u;
            A[kt][3] = v1 ? *(const unsigned*)&g_xh[(size_t)row1 * 64 + k0 + 8] : 0u;
        }
    }

    float acc[8][4];
#pragma unroll
    for (int nt = 0; nt < 8; nt++)
#pragma unroll
        for (int j = 0; j < 4; j++) acc[nt][j] = 0.f;

#pragma unroll
    for (int nt = 0; nt < 8; nt++) {
        int n = nt * 8 + r;
#pragma unroll
        for (int kt = 0; kt < 4; kt++) {
            unsigned b0 = *(const unsigned*)&Wt[n * 72 + kt * 16 + q2];
            unsigned b1 = *(const unsigned*)&Wt[n * 72 + kt * 16 + q2 + 8];
            asm volatile(
                "mma.sync.aligned.m16n8k16.row.col.f32.f16.f16.f32 "
                "{%0,%1,%2,%3}, {%4,%5,%6,%7}, {%8,%9}, {%0,%1,%2,%3};"
                : "+f"(acc[nt][0]), "+f"(acc[nt][1]), "+f"(acc[nt][2]), "+f"(acc[nt][3])
                : "r"(A[kt][0]), "r"(A[kt][1]), "r"(A[kt][2]), "r"(A[kt][3]),
                  "r"(b0), "r"(b1));
        }
    }

#pragma unroll
    for (int nt = 0; nt < 8; nt++) {
        int col = nt * 8 + q2;
        if (v0) *(__half2*)&g_yh[(size_t)row0 * 64 + col] = __floats2half2_rn(acc[nt][0], acc[nt][1]);
        if (v1) *(__half2*)&g_yh[(size_t)row1 * 64 + col] = __floats2half2_rn(acc[nt][2], acc[nt][3]);
    }
}

// ---------------- fused aggregation + bias + ReLU + BN + residual ------------
__device__ __forceinline__ float4 h4_to_f4(uint2 u) {
    float2 lo = __half22float2(*(__half2*)&u.x);
    float2 hi = __half22float2(*(__half2*)&u.y);
    return make_float4(lo.x, lo.y, hi.x, hi.y);
}

__global__ void __launch_bounds__(256) k_agg(int res_sel, int out_sel,
                                             const float* __restrict__ bias,
                                             const float* __restrict__ gamma,
                                             const float* __restrict__ beta,
                                             const float* __restrict__ mean,
                                             const float* __restrict__ var) {
    int gw   = (blockIdx.x * blockDim.x + threadIdx.x) >> 5;
    int lane = threadIdx.x & 31;
    int node = gw * 2 + (lane >> 4);
    if (node >= N_NODES) return;
    int q = lane & 15;

    const __half* Yh  = g_yh;
    float*        OUT = out_sel ? g_xb : g_xa;
    const float*  RES = (res_sel < 0) ? nullptr
                                      : (res_sel == 0 ? (const float*)g_xa : (const float*)g_xb);

    int beg = g_rowptr[node], end = g_rowptr[node + 1];
    float4 a = make_float4(0.f, 0.f, 0.f, 0.f);

    int e = beg;
    for (; e + 3 < end; e += 4) {
        int2 c0 = g_csr[e];
        int2 c1 = g_csr[e + 1];
        int2 c2 = g_csr[e + 2];
        int2 c3 = g_csr[e + 3];
        uint2 u0 = ((const uint2*)(Yh + (size_t)c0.x * 64))[q];
        uint2 u1 = ((const uint2*)(Yh + (size_t)c1.x * 64))[q];
        uint2 u2 = ((const uint2*)(Yh + (size_t)c2.x * 64))[q];
        uint2 u3 = ((const uint2*)(Yh + (size_t)c3.x * 64))[q];
        float4 v0 = h4_to_f4(u0), v1 = h4_to_f4(u1);
        float4 v2 = h4_to_f4(u2), v3 = h4_to_f4(u3);
        float w0 = __int_as_float(c0.y), w1 = __int_as_float(c1.y);
        float w2 = __int_as_float(c2.y), w3 = __int_as_float(c3.y);
        a.x += w0 * v0.x + w1 * v1.x + w2 * v2.x + w3 * v3.x;
        a.y += w0 * v0.y + w1 * v1.y + w2 * v2.y + w3 * v3.y;
        a.z += w0 * v0.z + w1 * v1.z + w2 * v2.z + w3 * v3.z;
        a.w += w0 * v0.w + w1 * v1.w + w2 * v2.w + w3 * v3.w;
    }
    for (; e < end; e++) {
        int2 c0 = g_csr[e];
        uint2 u0 = ((const uint2*)(Yh + (size_t)c0.x * 64))[q];
        float4 v0 = h4_to_f4(u0);
        float w0 = __int_as_float(c0.y);
        a.x += w0 * v0.x;  a.y += w0 * v0.y;
        a.z += w0 * v0.z;  a.w += w0 * v0.w;
    }

    float  di = g_dinv[node];
    float4 self = h4_to_f4(((const uint2*)(Yh + (size_t)node * 64))[q]);
    float4 b  = ((const float4*)bias)[q];
    a.x = di * (a.x + di * self.x) + b.x;
    a.y = di * (a.y + di * self.y) + b.y;
    a.z = di * (a.z + di * self.z) + b.z;
    a.w = di * (a.w + di * self.w) + b.w;
    a.x = fmaxf(a.x, 0.f); a.y = fmaxf(a.y, 0.f);
    a.z = fmaxf(a.z, 0.f); a.w = fmaxf(a.w, 0.f);

    float4 ga = ((const float4*)gamma)[q];
    float4 be = ((const float4*)beta)[q];
    float4 mm = ((const float4*)mean)[q];
    float4 vv = ((const float4*)var)[q];
    float4 sc;
    sc.x = ga.x * rsqrtf(vv.x + EPSV);
    sc.y = ga.y * rsqrtf(vv.y + EPSV);
    sc.z = ga.z * rsqrtf(vv.z + EPSV);
    sc.w = ga.w * rsqrtf(vv.w + EPSV);
    a.x = (a.x - mm.x) * sc.x + be.x;
    a.y = (a.y - mm.y) * sc.y + be.y;
    a.z = (a.z - mm.z) * sc.z + be.z;
    a.w = (a.w - mm.w) * sc.w + be.w;

    if (RES) {
        float4 rr = ((const float4*)(RES + (size_t)node * 64))[q];
        a.x += rr.x; a.y += rr.y; a.z += rr.z; a.w += rr.w;
    }
    ((float4*)(OUT + (size_t)node * 64))[q] = a;

    // fp16 copy for next layer's tensor-core A
    uint2 up;
    __half2 h01 = __floats2half2_rn(a.x, a.y);
    __half2 h23 = __floats2half2_rn(a.z, a.w);
    up.x = *(unsigned*)&h01;
    up.y = *(unsigned*)&h23;
    ((uint2*)(g_xh + (size_t)node * 64))[q] = up;
}

// ---------------- pooling (batch sorted -> run-length accumulate) ------------
__global__ void k_pool(const int* __restrict__ batch) {
    const float* X5 = (const float*)g_xa;
    int c = threadIdx.x;
    int start = blockIdx.x * 512;
    if (start >= N_NODES) return;
    int endn = min(start + 512, N_NODES);
    float acc = 0.f;
    int run = 0;
    int gcur = batch[start];
    for (int n = start; n < endn; n++) {
        int g = batch[n];
        if (g != gcur) {
            atomicAdd(&g_ssum[gcur * 64 + c], acc);
            if (c == 0) atomicAdd(&g_cnt[gcur], (float)run);
            acc = 0.f; run = 0; gcur = g;
        }
        acc += X5[n * 64 + c];
        run++;
    }
    atomicAdd(&g_ssum[gcur * 64 + c], acc);
    if (c == 0) atomicAdd(&g_cnt[gcur], (float)run);
}

// ---------------- MLP head ---------------------------------------------------
__global__ void k_head(const float* __restrict__ hW1, const float* __restrict__ hb1,
                       const float* __restrict__ hg,  const float* __restrict__ hbeta,
                       const float* __restrict__ hm,  const float* __restrict__ hv,
                       const float* __restrict__ hW2, const float* __restrict__ hb2,
                       float* __restrict__ out) {
    int g = threadIdx.x;
    if (g >= N_GRAPHS) return;
    float inv = 1.f / fmaxf(g_cnt[g], 1.f);
    float gv[64];
#pragma unroll
    for (int k = 0; k < 64; k++) gv[k] = g_ssum[g * 64 + k] * inv;
    float o = hb2[0];
    for (int j = 0; j < 32; j++) {
        float s = hb1[j];
#pragma unroll
        for (int k = 0; k < 64; k++) s += gv[k] * hW1[k * 32 + j];
        s = fmaxf(s, 0.f);
        s = (s - hm[j]) * (hg[j] * rsqrtf(hv[j] + EPSV)) + hbeta[j];
        o += s * hW2[j];
    }
    out[g] = o;
}

// ---------------- launcher ---------------------------------------------------
extern "C" void kernel_launch(void* const* d_in, const int* in_sizes, int n_in,
                              void* d_out, int out_size) {
    const float* x     = (const float*)d_in[0];
    const int*   ei    = (const int*)  d_in[1];
    const int*   batch = (const int*)  d_in[2];
    const float* Wc    = (const float*)d_in[3];
    const float* bc    = (const float*)d_in[4];
    const float* bn_g  = (const float*)d_in[5];
    const float* bn_b  = (const float*)d_in[6];
    const float* bn_m  = (const float*)d_in[7];
    const float* bn_v  = (const float*)d_in[8];
    const float* hW1   = (const float*)d_in[9];
    const float* hb1   = (const float*)d_in[10];
    const float* hg    = (const float*)d_in[11];
    const float* hbe   = (const float*)d_in[12];
    const float* hm    = (const float*)d_in[13];
    const float* hv    = (const float*)d_in[14];
    const float* hW2   = (const float*)d_in[15];
    const float* hb2   = (const float*)d_in[16];
    float* out = (float*)d_out;

    const int* src = ei;
    const int* dst = ei + N_EDGES;

    // zero degree array (stream-ordered memset; graph-capturable)
    void* deg_ptr = nullptr;
    cudaGetSymbolAddress(&deg_ptr, g_deg);
    cudaMemsetAsync(deg_ptr, 0, N_NODES * sizeof(int));

    // --- CSR build: 3 kernels (first gemm = kernel index 3 for ncu) ---
    k_count  <<<(N_EDGES + 255) / 256, 256>>>(dst);
    k_scan   <<<(N_NODES + 511) / 512, 512>>>();
    k_scatter<<<(N_EDGES + 255) / 256, 256>>>(src, dst);

    // --- 5 GCN layers ---
    const int gemm_grid = (N_NODES + 63) / 64;                  // 1563
    const int agg_grid  = ((N_NODES + 1) / 2 * 32 + 255) / 256; // 2 nodes/warp

    k_gemm<<<gemm_grid, 128>>>(x, 1, Wc + 0 * 4096);
    k_agg <<<agg_grid, 256>>>(-1, 0, bc + 0, bn_g + 0, bn_b + 0, bn_m + 0, bn_v + 0);
    k_gemm<<<gemm_grid, 128>>>(nullptr, 0, Wc + 1 * 4096);
    k_agg <<<agg_grid, 256>>>(0, 1, bc + 64, bn_g + 64, bn_b + 64, bn_m + 64, bn_v + 64);
    k_gemm<<<gemm_grid, 128>>>(nullptr, 0, Wc + 2 * 4096);
    k_agg <<<agg_grid, 256>>>(1, 0, bc + 128, bn_g + 128, bn_b + 128, bn_m + 128, bn_v + 128);
    k_gemm<<<gemm_grid, 128>>>(nullptr, 0, Wc + 3 * 4096);
    k_agg <<<agg_grid, 256>>>(0, 1, bc + 192, bn_g + 192, bn_b + 192, bn_m + 192, bn_v + 192);
    k_gemm<<<gemm_grid, 128>>>(nullptr, 0, Wc + 4 * 4096);
    k_agg <<<agg_grid, 256>>>(1, 0, bc + 256, bn_g + 256, bn_b + 256, bn_m + 256, bn_v + 256);

    // --- pool + head ---
    k_pool<<<(N_NODES + 511) / 512, 64>>>(batch);
    k_head<<<1, 64>>>(hW1, hb1, hg, hbe, hm, hv, hW2, hb2, out);
}

// round 7
// speedup vs baseline: 1.2500x; 1.2500x over previous
#include <cuda_runtime.h>
#include <cuda_fp16.h>

#define N_NODES 100000
#define N_EDGES 1000000
#define N_GRAPHS 64
#define HD 64
#define EPSV 1e-5f

// ---------------- scratch (device globals; no allocation allowed) ------------
__device__ __half g_yh[N_NODES * HD];  // GEMM output (fp16, randomly gathered)
__device__ float g_xa[N_NODES * HD];   // ping (fp32 layer outputs)
__device__ float g_xb[N_NODES * HD];   // pong
__device__ int   g_deg[N_NODES];       // zeroed at end of each run (BSS-zero first run)
__device__ float g_dinv[N_NODES];
__device__ int   g_rowptr[N_NODES + 1];
__device__ int   g_cursor[N_NODES];
__device__ int2  g_csr[N_EDGES];       // .x = src node, .y = bits of dinv[src]
__device__ int   g_partial[256];       // scan lookback state (agg+1, 0=not ready)
__device__ float g_ssum[N_GRAPHS * HD];
__device__ float g_cnt[N_GRAPHS];
__device__ int   g_sync1;              // device-wide barrier arrive count
__device__ int   g_sync2;              // device-wide barrier pass count
__device__ int   g_pdone;              // pool blocks done

// ---------------- kernel 0: degree count + zero pool/scan state --------------
__global__ void k_count(const int* __restrict__ dst) {
    int e = blockIdx.x * blockDim.x + threadIdx.x;
    if (e < N_EDGES) atomicAdd(&g_deg[dst[e]], 1);
    if (e < N_GRAPHS * HD) g_ssum[e] = 0.f;
    if (e < N_GRAPHS)      g_cnt[e]  = 0.f;
    if (e < 256)           g_partial[e] = 0;
}

// ---------------- kernel 1: scan + dinv + device barrier + scatter -----------
// 196 blocks x 512 (all concurrently resident: 4 blocks/SM limit > 196/148).
// Phase 1: decoupled-lookback scan of degrees -> rowptr/cursor, dinv, deg=0.
// Barrier: counter-based, self-resetting (safe: last passer resets).
// Phase 2: grid-stride scatter of edges into CSR.
__global__ void __launch_bounds__(512) k_scan_scatter(const int* __restrict__ src,
                                                      const int* __restrict__ dst) {
    __shared__ int sh[512];
    __shared__ int shp[256];
    int tid = threadIdx.x;
    int bid = blockIdx.x;
    int i = bid * 512 + tid;

    int v = (i < N_NODES) ? g_deg[i] : 0;        // edge count (no self loop)
    if (i < N_NODES) {
        g_dinv[i] = rsqrtf((float)(v + 1));
        g_deg[i]  = 0;                           // re-zero for next replay
    }

    sh[tid] = v;
    __syncthreads();
    for (int off = 1; off < 512; off <<= 1) {
        int t = (tid >= off) ? sh[tid - off] : 0;
        __syncthreads();
        sh[tid] += t;
        __syncthreads();
    }
    int incl  = sh[tid];
    int total = sh[511];

    if (tid == 0) {                               // publish aggregate
        __threadfence();
        atomicExch(&g_partial[bid], total + 1);
    }

    if (tid < 256) {                              // parallel spin on predecessors
        int p = 0;
        if (tid < bid) {
            do { p = atomicAdd(&g_partial[tid], 0); } while (p == 0);
            p -= 1;
        }
        shp[tid] = p;
    }
    __syncthreads();
    for (int off = 128; off > 0; off >>= 1) {
        if (tid < off) shp[tid] += shp[tid + off];
        __syncthreads();
    }
    int offset = shp[0];

    if (i < N_NODES) {
        int ex = offset + incl - v;
        g_rowptr[i] = ex;
        g_cursor[i] = ex;
    }
    if (bid == 0 && tid == 0) g_rowptr[N_NODES] = N_EDGES;

    // ---- device-wide barrier (self-resetting) ----
    __threadfence();
    __syncthreads();
    if (tid == 0) {
        atomicAdd(&g_sync1, 1);
        while (atomicAdd(&g_sync1, 0) < (int)gridDim.x) {}
        int p = atomicAdd(&g_sync2, 1);
        if (p == (int)gridDim.x - 1) {            // last to pass: everyone is out
            g_sync1 = 0;
            g_sync2 = 0;
            __threadfence();
        }
    }
    __syncthreads();

    // ---- phase 2: scatter edges into CSR ----
    int stride = gridDim.x * 512;
    for (int e = i; e < N_EDGES; e += stride) {
        int d = dst[e];
        int s = src[e];
        int p = atomicAdd(&g_cursor[d], 1);
        g_csr[p] = make_int2(s, __float_as_int(g_dinv[s]));
    }
}

// ---------------- GEMM: Yh = half(X @ W) via packed fma.rn.f32x2 -------------
// (proven R5 version: fp32 inputs, fp16 output only for the gathered tensor)
__global__ void __launch_bounds__(256) k_gemm(const float* __restrict__ Xext, int xsel,
                                              const float* __restrict__ W) {
    __shared__ float xs[64 * 128];
    const float* X = (xsel < 0) ? Xext : (xsel == 0 ? (const float*)g_xa : (const float*)g_xb);

    int tid  = threadIdx.x;
    int c    = tid & 63;
    int rsub = tid >> 6;

    float w[64];
#pragma unroll
    for (int k = 0; k < 64; k++) w[k] = W[k * 64 + c];

    int rt = blockIdx.x * 128;
#pragma unroll
    for (int it = 0; it < 8; it++) {
        int idx = it * 256 + tid;
        int cq  = idx & 15;
        int row = idx >> 4;
        int grow = rt + row;
        float4 x4 = make_float4(0.f, 0.f, 0.f, 0.f);
        if (grow < N_NODES) x4 = *(const float4*)&X[grow * 64 + 4 * cq];
        int u  = row >> 1;
        int rb = row & 1;
        float vals[4] = {x4.x, x4.y, x4.z, x4.w};
#pragma unroll
        for (int m = 0; m < 4; m++) {
            int K  = 4 * cq + m;
            int gk = (K + (K >> 2)) & 15;
            xs[K * 128 + 2 * (u ^ gk) + rb] = vals[m];
        }
    }
    __syncthreads();

    unsigned long long acc[16];
#pragma unroll
    for (int j = 0; j < 16; j++) acc[j] = 0ULL;

#pragma unroll
    for (int k = 0; k < 64; k++) {
        const int g = (k + (k >> 2)) & 15;
        unsigned long long wp;
        asm("mov.b64 %0, {%1, %1};" : "=l"(wp) : "f"(w[k]));
        const float* base = &xs[k * 128 + rsub * 32];
#pragma unroll
        for (int j = 0; j < 16; j++) {
            float2 x2 = *(const float2*)&base[2 * (j ^ g)];
            unsigned long long xv;
            asm("mov.b64 %0, {%1, %2};" : "=l"(xv) : "f"(x2.x), "f"(x2.y));
            asm("fma.rn.f32x2 %0, %1, %2, %0;" : "+l"(acc[j]) : "l"(xv), "l"(wp));
        }
    }

#pragma unroll
    for (int j = 0; j < 16; j++) {
        int row = rt + rsub * 32 + 2 * j;
        float lo, hi;
        asm("mov.b64 {%0, %1}, %2;" : "=f"(lo), "=f"(hi) : "l"(acc[j]));
        if (row < N_NODES)     g_yh[row * 64 + c]       = __float2half_rn(lo);
        if (row + 1 < N_NODES) g_yh[(row + 1) * 64 + c] = __float2half_rn(hi);
    }
}

// ---------------- fused aggregation + bias + ReLU + BN + residual ------------
// (proven R5 version) 2 nodes per warp; lane handles 4 dims (uint2 = 4 halves).
__device__ __forceinline__ float4 h4_to_f4(uint2 u) {
    float2 lo = __half22float2(*(__half2*)&u.x);
    float2 hi = __half22float2(*(__half2*)&u.y);
    return make_float4(lo.x, lo.y, hi.x, hi.y);
}

__global__ void __launch_bounds__(256) k_agg(int res_sel, int out_sel,
                                             const float* __restrict__ bias,
                                             const float* __restrict__ gamma,
                                             const float* __restrict__ beta,
                                             const float* __restrict__ mean,
                                             const float* __restrict__ var) {
    int gw   = (blockIdx.x * blockDim.x + threadIdx.x) >> 5;
    int lane = threadIdx.x & 31;
    int node = gw * 2 + (lane >> 4);
    if (node >= N_NODES) return;
    int q = lane & 15;

    const __half* Yh  = g_yh;
    float*        OUT = out_sel ? g_xb : g_xa;
    const float*  RES = (res_sel < 0) ? nullptr
                                      : (res_sel == 0 ? (const float*)g_xa : (const float*)g_xb);

    int beg = g_rowptr[node], end = g_rowptr[node + 1];
    float4 a = make_float4(0.f, 0.f, 0.f, 0.f);

    int e = beg;
    for (; e + 3 < end; e += 4) {
        int2 c0 = g_csr[e];
        int2 c1 = g_csr[e + 1];
        int2 c2 = g_csr[e + 2];
        int2 c3 = g_csr[e + 3];
        uint2 u0 = ((const uint2*)(Yh + (size_t)c0.x * 64))[q];
        uint2 u1 = ((const uint2*)(Yh + (size_t)c1.x * 64))[q];
        uint2 u2 = ((const uint2*)(Yh + (size_t)c2.x * 64))[q];
        uint2 u3 = ((const uint2*)(Yh + (size_t)c3.x * 64))[q];
        float4 v0 = h4_to_f4(u0), v1 = h4_to_f4(u1);
        float4 v2 = h4_to_f4(u2), v3 = h4_to_f4(u3);
        float w0 = __int_as_float(c0.y), w1 = __int_as_float(c1.y);
        float w2 = __int_as_float(c2.y), w3 = __int_as_float(c3.y);
        a.x += w0 * v0.x + w1 * v1.x + w2 * v2.x + w3 * v3.x;
        a.y += w0 * v0.y + w1 * v1.y + w2 * v2.y + w3 * v3.y;
        a.z += w0 * v0.z + w1 * v1.z + w2 * v2.z + w3 * v3.z;
        a.w += w0 * v0.w + w1 * v1.w + w2 * v2.w + w3 * v3.w;
    }
    for (; e < end; e++) {
        int2 c0 = g_csr[e];
        uint2 u0 = ((const uint2*)(Yh + (size_t)c0.x * 64))[q];
        float4 v0 = h4_to_f4(u0);
        float w0 = __int_as_float(c0.y);
        a.x += w0 * v0.x;  a.y += w0 * v0.y;
        a.z += w0 * v0.z;  a.w += w0 * v0.w;
    }

    float  di = g_dinv[node];
    float4 self = h4_to_f4(((const uint2*)(Yh + (size_t)node * 64))[q]);
    float4 b  = ((const float4*)bias)[q];
    a.x = di * (a.x + di * self.x) + b.x;
    a.y = di * (a.y + di * self.y) + b.y;
    a.z = di * (a.z + di * self.z) + b.z;
    a.w = di * (a.w + di * self.w) + b.w;
    a.x = fmaxf(a.x, 0.f); a.y = fmaxf(a.y, 0.f);
    a.z = fmaxf(a.z, 0.f); a.w = fmaxf(a.w, 0.f);

    float4 ga = ((const float4*)gamma)[q];
    float4 be = ((const float4*)beta)[q];
    float4 mm = ((const float4*)mean)[q];
    float4 vv = ((const float4*)var)[q];
    float4 sc;
    sc.x = ga.x * rsqrtf(vv.x + EPSV);
    sc.y = ga.y * rsqrtf(vv.y + EPSV);
    sc.z = ga.z * rsqrtf(vv.z + EPSV);
    sc.w = ga.w * rsqrtf(vv.w + EPSV);
    a.x = (a.x - mm.x) * sc.x + be.x;
    a.y = (a.y - mm.y) * sc.y + be.y;
    a.z = (a.z - mm.z) * sc.z + be.z;
    a.w = (a.w - mm.w) * sc.w + be.w;

    if (RES) {
        float4 rr = ((const float4*)(RES + (size_t)node * 64))[q];
        a.x += rr.x; a.y += rr.y; a.z += rr.z; a.w += rr.w;
    }
    ((float4*)(OUT + (size_t)node * 64))[q] = a;
}

// ---------------- pooling + MLP head (fused via last-block-done) -------------
__global__ void k_pool_head(const int* __restrict__ batch,
                            const float* __restrict__ hW1, const float* __restrict__ hb1,
                            const float* __restrict__ hg,  const float* __restrict__ hbeta,
                            const float* __restrict__ hm,  const float* __restrict__ hv,
                            const float* __restrict__ hW2, const float* __restrict__ hb2,
                            float* __restrict__ out) {
    const float* X5 = (const float*)g_xa;
    int c = threadIdx.x;
    int start = blockIdx.x * 512;
    if (start < N_NODES) {
        int endn = min(start + 512, N_NODES);
        float acc = 0.f;
        int run = 0;
        int gcur = batch[start];
        for (int n = start; n < endn; n++) {
            int g = batch[n];
            if (g != gcur) {
                atomicAdd(&g_ssum[gcur * 64 + c], acc);
                if (c == 0) atomicAdd(&g_cnt[gcur], (float)run);
                acc = 0.f; run = 0; gcur = g;
            }
            acc += X5[n * 64 + c];
            run++;
        }
        atomicAdd(&g_ssum[gcur * 64 + c], acc);
        if (c == 0) atomicAdd(&g_cnt[gcur], (float)run);
    }

    // last-block-done -> run head
    __threadfence();
    __shared__ int lastf;
    if (threadIdx.x == 0) {
        int d = atomicAdd(&g_pdone, 1);
        lastf = (d == (int)gridDim.x - 1);
        if (lastf) g_pdone = 0;                   // reset for next replay
    }
    __syncthreads();
    if (!lastf) return;

    int g = threadIdx.x;                          // 64 threads = 64 graphs
    float inv = 1.f / fmaxf(g_cnt[g], 1.f);
    float gv[64];
#pragma unroll
    for (int k = 0; k < 64; k++) gv[k] = g_ssum[g * 64 + k] * inv;
    float o = hb2[0];
    for (int j = 0; j < 32; j++) {
        float s = hb1[j];
#pragma unroll
        for (int k = 0; k < 64; k++) s += gv[k] * hW1[k * 32 + j];
        s = fmaxf(s, 0.f);
        s = (s - hm[j]) * (hg[j] * rsqrtf(hv[j] + EPSV)) + hbeta[j];
        o += s * hW2[j];
    }
    out[g] = o;
}

// ---------------- launcher ---------------------------------------------------
extern "C" void kernel_launch(void* const* d_in, const int* in_sizes, int n_in,
                              void* d_out, int out_size) {
    const float* x     = (const float*)d_in[0];
    const int*   ei    = (const int*)  d_in[1];
    const int*   batch = (const int*)  d_in[2];
    const float* Wc    = (const float*)d_in[3];
    const float* bc    = (const float*)d_in[4];
    const float* bn_g  = (const float*)d_in[5];
    const float* bn_b  = (const float*)d_in[6];
    const float* bn_m  = (const float*)d_in[7];
    const float* bn_v  = (const float*)d_in[8];
    const float* hW1   = (const float*)d_in[9];
    const float* hb1   = (const float*)d_in[10];
    const float* hg    = (const float*)d_in[11];
    const float* hbe   = (const float*)d_in[12];
    const float* hm    = (const float*)d_in[13];
    const float* hv    = (const float*)d_in[14];
    const float* hW2   = (const float*)d_in[15];
    const float* hb2   = (const float*)d_in[16];
    float* out = (float*)d_out;

    const int* src = ei;
    const int* dst = ei + N_EDGES;

    // --- CSR build: 2 kernels (so kernel index 3 = first k_agg for ncu) ---
    k_count       <<<(N_EDGES + 255) / 256, 256>>>(dst);
    k_scan_scatter<<<(N_NODES + 511) / 512, 512>>>(src, dst);

    // --- 5 GCN layers ---
    const int gemm_grid = (N_NODES + 127) / 128;                // 782
    const int agg_grid  = ((N_NODES + 1) / 2 * 32 + 255) / 256; // 2 nodes/warp

    k_gemm<<<gemm_grid, 256>>>(x, -1, Wc + 0 * 4096);
    k_agg <<<agg_grid, 256>>>(-1, 0, bc + 0, bn_g + 0, bn_b + 0, bn_m + 0, bn_v + 0);
    k_gemm<<<gemm_grid, 256>>>(nullptr, 0, Wc + 1 * 4096);
    k_agg <<<agg_grid, 256>>>(0, 1, bc + 64, bn_g + 64, bn_b + 64, bn_m + 64, bn_v + 64);
    k_gemm<<<gemm_grid, 256>>>(nullptr, 1, Wc + 2 * 4096);
    k_agg <<<agg_grid, 256>>>(1, 0, bc + 128, bn_g + 128, bn_b + 128, bn_m + 128, bn_v + 128);
    k_gemm<<<gemm_grid, 256>>>(nullptr, 0, Wc + 3 * 4096);
    k_agg <<<agg_grid, 256>>>(0, 1, bc + 192, bn_g + 192, bn_b + 192, bn_m + 192, bn_v + 192);
    k_gemm<<<gemm_grid, 256>>>(nullptr, 1, Wc + 4 * 4096);
    k_agg <<<agg_grid, 256>>>(1, 0, bc + 256, bn_g + 256, bn_b + 256, bn_m + 256, bn_v + 256);

    // --- pool + head (fused) ---
    k_pool_head<<<(N_NODES + 511) / 512, 64>>>(batch, hW1, hb1, hg, hbe, hm, hv, hW2, hb2, out);
}